// round 1
// baseline (speedup 1.0000x reference)
#include <cuda_runtime.h>
#include <cuda_bf16.h>

// Problem constants
#define BSZ     2
#define HEADS   8
#define HH      64
#define WWW     64
#define DIM     32
#define SEQ     4096          // HH*WWW
#define QTILE   128           // queries per CTA (1 per thread)
#define KTILE   64            // keys per tile = one p-row
#define NTHREADS 128
#define EPAD    65            // padded row stride for qeh/qew tables

// Dynamic smem layout (floats):
//   sK   : KTILE*DIM            = 2048
//   sV   : KTILE*DIM            = 2048
//   sQEH : QTILE*EPAD           = 8320
//   sQEW : QTILE*EPAD           = 8320
// total = 20736 floats = 82944 bytes  -> 2 CTAs / SM
#define SMEM_FLOATS (2*KTILE*DIM + 2*QTILE*EPAD)

__global__ void __launch_bounds__(NTHREADS, 2)
abspos_attn_kernel(const float* __restrict__ q,
                   const float* __restrict__ k,
                   const float* __restrict__ v,
                   const float* __restrict__ eh,
                   const float* __restrict__ ew,
                   float* __restrict__ out)
{
    extern __shared__ float smem[];
    float*  sK   = smem;
    float*  sV   = sK + KTILE * DIM;
    float*  sQEH = sV + KTILE * DIM;
    float*  sQEW = sQEH + QTILE * EPAD;
    float4* sK4  = reinterpret_cast<float4*>(sK);
    float4* sV4  = reinterpret_cast<float4*>(sV);

    const int tid  = threadIdx.x;
    const int bn   = blockIdx.y;                 // 0..15  (b*HEADS + n)
    const int qidx = blockIdx.x * QTILE + tid;   // flattened query (x*64+y)

    // ---- load this thread's query, pre-scaled by 1/sqrt(DIM) ----
    const float scale = 0.17677669529663687f;    // 32^-0.5
    float4 qr[DIM / 4];
    {
        const float4* qg = reinterpret_cast<const float4*>(
            q + ((size_t)bn * SEQ + qidx) * DIM);
        #pragma unroll
        for (int i = 0; i < DIM / 4; i++) {
            float4 t = qg[i];
            t.x *= scale; t.y *= scale; t.z *= scale; t.w *= scale;
            qr[i] = t;
        }
    }

    // ---- per-query positional tables: qeh[p] = q.emb_h[p], qew[j] = q.emb_w[j]
    // (each thread writes & reads only its own padded row -> no sync needed)
    {
        float* myQEH = sQEH + tid * EPAD;
        float* myQEW = sQEW + tid * EPAD;
        for (int p = 0; p < 64; p++) {
            const float4* e = reinterpret_cast<const float4*>(eh + p * DIM);
            float s = 0.f;
            #pragma unroll
            for (int i = 0; i < DIM / 4; i++) {
                float4 ev = e[i];
                s = fmaf(qr[i].x, ev.x, s); s = fmaf(qr[i].y, ev.y, s);
                s = fmaf(qr[i].z, ev.z, s); s = fmaf(qr[i].w, ev.w, s);
            }
            myQEH[p] = s;
        }
        for (int p = 0; p < 64; p++) {
            const float4* e = reinterpret_cast<const float4*>(ew + p * DIM);
            float s = 0.f;
            #pragma unroll
            for (int i = 0; i < DIM / 4; i++) {
                float4 ev = e[i];
                s = fmaf(qr[i].x, ev.x, s); s = fmaf(qr[i].y, ev.y, s);
                s = fmaf(qr[i].z, ev.z, s); s = fmaf(qr[i].w, ev.w, s);
            }
            myQEW[p] = s;
        }
    }

    // ---- online softmax state ----
    float  m = -1e30f, l = 0.f;
    float4 acc[DIM / 4];
    #pragma unroll
    for (int i = 0; i < DIM / 4; i++) acc[i] = make_float4(0.f, 0.f, 0.f, 0.f);

    const float* kbase = k + (size_t)bn * SEQ * DIM;
    const float* vbase = v + (size_t)bn * SEQ * DIM;
    const float* myQEW = sQEW + tid * EPAD;
    const float* myQEH = sQEH + tid * EPAD;

    for (int t = 0; t < SEQ / KTILE; t++) {
        __syncthreads();   // retire reads of previous tile
        {
            const float4* kg = reinterpret_cast<const float4*>(kbase + t * KTILE * DIM);
            const float4* vg = reinterpret_cast<const float4*>(vbase + t * KTILE * DIM);
            #pragma unroll
            for (int i = 0; i < (KTILE * DIM / 4) / NTHREADS; i++) {
                sK4[tid + i * NTHREADS] = kg[tid + i * NTHREADS];
                sV4[tid + i * NTHREADS] = vg[tid + i * NTHREADS];
            }
        }
        __syncthreads();

        const float bh = myQEH[t];   // bias row component for this p-row

        #pragma unroll 1
        for (int j0 = 0; j0 < KTILE; j0 += 8) {
            // ---- scores for 8 keys (ILP across 8 accumulators) ----
            float s[8];
            #pragma unroll
            for (int jj = 0; jj < 8; jj++) s[jj] = bh + myQEW[j0 + jj];
            #pragma unroll
            for (int d4 = 0; d4 < DIM / 4; d4++) {
                const float4 qv = qr[d4];
                #pragma unroll
                for (int jj = 0; jj < 8; jj++) {
                    float4 kv = sK4[(j0 + jj) * (DIM / 4) + d4];
                    s[jj] = fmaf(qv.x, kv.x, s[jj]);
                    s[jj] = fmaf(qv.y, kv.y, s[jj]);
                    s[jj] = fmaf(qv.z, kv.z, s[jj]);
                    s[jj] = fmaf(qv.w, kv.w, s[jj]);
                }
            }
            // ---- online softmax update ----
            float mt = m;
            #pragma unroll
            for (int jj = 0; jj < 8; jj++) mt = fmaxf(mt, s[jj]);
            const float f = __expf(m - mt);
            m = mt;
            float p[8], ls = 0.f;
            #pragma unroll
            for (int jj = 0; jj < 8; jj++) { p[jj] = __expf(s[jj] - mt); ls += p[jj]; }
            l = fmaf(l, f, ls);
            // ---- rescale + accumulate PV ----
            #pragma unroll
            for (int d4 = 0; d4 < DIM / 4; d4++) {
                float4 a = acc[d4];
                a.x *= f; a.y *= f; a.z *= f; a.w *= f;
                #pragma unroll
                for (int jj = 0; jj < 8; jj++) {
                    float4 vv = sV4[(j0 + jj) * (DIM / 4) + d4];
                    a.x = fmaf(p[jj], vv.x, a.x);
                    a.y = fmaf(p[jj], vv.y, a.y);
                    a.z = fmaf(p[jj], vv.z, a.z);
                    a.w = fmaf(p[jj], vv.w, a.w);
                }
                acc[d4] = a;
            }
        }
    }

    // ---- write out: out[b, x, y, n*DIM + d] ----
    const float inv = 1.f / l;
    const int b = bn / HEADS, n = bn % HEADS;
    float4* og = reinterpret_cast<float4*>(
        out + ((size_t)b * SEQ + qidx) * (HEADS * DIM) + n * DIM);
    #pragma unroll
    for (int d4 = 0; d4 < DIM / 4; d4++) {
        float4 a = acc[d4];
        a.x *= inv; a.y *= inv; a.z *= inv; a.w *= inv;
        og[d4] = a;
    }
}

extern "C" void kernel_launch(void* const* d_in, const int* in_sizes, int n_in,
                              void* d_out, int out_size)
{
    const float* q  = (const float*)d_in[0];
    const float* k  = (const float*)d_in[1];
    const float* v  = (const float*)d_in[2];
    const float* eh = (const float*)d_in[3];
    const float* ew = (const float*)d_in[4];
    float* out = (float*)d_out;

    const int smem_bytes = SMEM_FLOATS * (int)sizeof(float);
    static bool attr_set = false;
    if (!attr_set) {
        cudaFuncSetAttribute(abspos_attn_kernel,
                             cudaFuncAttributeMaxDynamicSharedMemorySize,
                             smem_bytes);
        attr_set = true;
    }

    dim3 grid(SEQ / QTILE, BSZ * HEADS);   // 32 x 16
    abspos_attn_kernel<<<grid, NTHREADS, smem_bytes>>>(q, k, v, eh, ew, out);
}